// round 15
// baseline (speedup 1.0000x reference)
#include <cuda_runtime.h>
#include <cuda_fp16.h>
#include <cstdint>
#include <math.h>

#define B_ 4
#define N_ 2048
#define C_ 64
#define H_ 512
#define W_ 512
#define GS 8
#define HG 64
#define WG 64
#define M_ 4096
#define EPSF 1e-8f

#define NT 128
#define CT 64
#define MSPLIT 4
#define CHUNK (M_ / MSPLIT)    // 1024
#define ITERS (CHUNK / CT)     // 16

#define PB_POS   512
#define PB_POOL  (HG / 4 * C_ * B_)        // 4096 (4 hg rows per block)
#define PREP_GRID (PB_POS + PB_POOL)

// ---------------- scratch ----------------
__device__ float g_cells[B_ * M_ * C_];
__device__ float g_dpos[B_ * N_];
__device__ float g_an[B_ * N_];
__device__ __half g_ah[B_ * N_ * C_];
__device__ __half g_bh[B_ * M_ * C_];
__device__ float g_top4[B_ * N_ * MSPLIT * 4];
__device__ float g_part2[32];

__device__ __forceinline__ void mma_f16(float (&d)[4], const uint32_t (&a)[4],
                                        uint32_t b0, uint32_t b1) {
    asm volatile(
        "mma.sync.aligned.m16n8k16.row.col.f32.f16.f16.f32 "
        "{%0,%1,%2,%3}, {%4,%5,%6,%7}, {%8,%9}, {%0,%1,%2,%3};"
        : "+f"(d[0]), "+f"(d[1]), "+f"(d[2]), "+f"(d[3])
        : "r"(a[0]), "r"(a[1]), "r"(a[2]), "r"(a[3]), "r"(b0), "r"(b1));
}

__device__ __forceinline__ void ldm_x4(uint32_t& r0, uint32_t& r1, uint32_t& r2,
                                       uint32_t& r3, uint32_t addr) {
    asm volatile("ldmatrix.sync.aligned.m8n8.x4.shared.b16 {%0,%1,%2,%3}, [%4];"
                 : "=r"(r0), "=r"(r1), "=r"(r2), "=r"(r3) : "r"(addr));
}

__device__ __forceinline__ void cp16(uint32_t dst, const void* src) {
    asm volatile("cp.async.cg.shared.global [%0], [%1], 16;" :: "r"(dst), "l"(src));
}
#define CP_COMMIT() asm volatile("cp.async.commit_group;" ::: "memory")
#define CP_WAIT(n)  asm volatile("cp.async.wait_group %0;" :: "n"(n) : "memory")

// branchy top-4 insert: common path (d2 >= t[3]) is a uniform not-taken branch.
__device__ __forceinline__ void ins4(float (&t)[4], float d2) {
    if (d2 < t[3]) {
        if (d2 < t[2]) {
            t[3] = t[2];
            if (d2 < t[1]) {
                t[2] = t[1];
                if (d2 < t[0]) { t[1] = t[0]; t[0] = d2; }
                else t[1] = d2;
            } else t[2] = d2;
        } else t[3] = d2;
    }
}

// ---------------- 1) fused prep: (pos + conv_a) + pool(float4) ----------------
__global__ void __launch_bounds__(512) prep_kernel(const float* __restrict__ wkp,
                                                   const float* __restrict__ kdesc,
                                                   const float* __restrict__ desc2) {
    int p   = blockIdx.x;
    int tid = threadIdx.x;

    if (p < PB_POS) {
        int lane = tid & 31;
        int idx  = p * 16 + (tid >> 5);
        int b    = idx / N_;

        float x = wkp[(size_t)idx * 2 + 0];
        float y = wkp[(size_t)idx * 2 + 1];
        x = fminf(fmaxf(x, 0.0f), (float)(W_ - 1));
        y = fminf(fmaxf(y, 0.0f), (float)(H_ - 1));
        float x0f = floorf(x), y0f = floorf(y);
        int x0 = (int)x0f, y0 = (int)y0f;
        int x1 = min(x0 + 1, W_ - 1), y1 = min(y0 + 1, H_ - 1);
        float wx = x - x0f, wy = y - y0f;
        float w00 = (1.f - wy) * (1.f - wx);
        float w01 = (1.f - wy) * wx;
        float w10 = wy * (1.f - wx);
        float w11 = wy * wx;

        float v[2];
        float ss = 0.f;
#pragma unroll
        for (int q = 0; q < 2; q++) {
            int c = lane + q * 32;
            const float* pp = desc2 + ((size_t)(b * C_ + c) * H_) * W_;
            float f00 = pp[(size_t)y0 * W_ + x0];
            float f01 = pp[(size_t)y0 * W_ + x1];
            float f10 = pp[(size_t)y1 * W_ + x0];
            float f11 = pp[(size_t)y1 * W_ + x1];
            v[q] = w00 * f00 + w01 * f01 + w10 * f10 + w11 * f11;
            ss += v[q] * v[q];
        }
#pragma unroll
        for (int o = 16; o; o >>= 1) ss += __shfl_xor_sync(0xffffffffu, ss, o);
        float inv = 1.0f / (sqrtf(ss) + EPSF);

        float dsum = 0.f, asum = 0.f;
#pragma unroll
        for (int q = 0; q < 2; q++) {
            int c = lane + q * 32;
            float av = kdesc[(size_t)idx * C_ + c];
            g_ah[(size_t)idx * C_ + c] = __float2half(av);   // fused conv_a
            float d  = av - v[q] * inv;
            dsum += d * d;
            asum += av * av;
        }
#pragma unroll
        for (int o = 16; o; o >>= 1) {
            dsum += __shfl_xor_sync(0xffffffffu, dsum, o);
            asum += __shfl_xor_sync(0xffffffffu, asum, o);
        }
        if (lane == 0) {
            g_dpos[idx] = sqrtf(dsum + EPSF);
            g_an[idx]   = asum;
        }
    } else {
        // pool: block handles (b, c, 4 hg rows); thread loads float4 per row.
        int q2    = p - PB_POS;            // 0..4095
        int hg4   = q2 & 15;
        int c     = (q2 >> 4) & 63;
        int b     = q2 >> 10;
        int strip = tid >> 7;              // 0..3
        int t     = tid & 127;             // 0..127 -> 4 columns each
        int hg    = hg4 * 4 + strip;

        const float4* pp = (const float4*)(desc2 +
            (((size_t)(b * C_ + c) * H_) + hg * GS) * W_) + t;
        float s = 0.f;
#pragma unroll
        for (int r = 0; r < GS; r++) {
            float4 v = pp[(size_t)r * (W_ / 4)];
            s += (v.x + v.y) + (v.z + v.w);
        }
        s += __shfl_xor_sync(0xffffffffu, s, 1);   // pair covers 8 cols = 1 cell
        if ((t & 1) == 0) {
            int wg = t >> 1;
            g_cells[((size_t)b * M_ + hg * WG + wg) * C_ + c] = s * (1.0f / 64.0f);
        }
    }
}

// ---------------- 2) normalize cells -> fp16 ----------------
__global__ void norm_kernel() {
    int idx  = blockIdx.x;
    int lane = threadIdx.x;
    const float* p = g_cells + (size_t)idx * C_;
    float v0 = p[lane], v1 = p[lane + 32];
    float ss = v0 * v0 + v1 * v1;
#pragma unroll
    for (int o = 16; o; o >>= 1) ss += __shfl_xor_sync(0xffffffffu, ss, o);
    float inv = 1.0f / (sqrtf(ss) + EPSF);
    g_bh[(size_t)idx * C_ + lane]      = __float2half(v0 * inv);
    g_bh[(size_t)idx * C_ + lane + 32] = __float2half(v1 * inv);
}

// ---------------- 3) HMMA fp16 GEMM + mask + top-4 (occ 3) ----------------
#define BSTRIDE_W 36   // words per padded cell row (72 fp16 = 144 B)

__global__ void __launch_bounds__(256, 3) mma_kernel(const float* __restrict__ wkp) {
    __shared__ uint4 sm_bh[2][CT * 9];

    int tid   = threadIdx.x;
    int w     = tid >> 5;
    int lane  = tid & 31;
    int g     = lane >> 2;
    int tig   = lane & 3;
    int ntile = blockIdx.x;
    int chunk = blockIdx.y;
    int b     = blockIdx.z;

    int mbase0 = chunk * CHUNK;

    int r0 = ntile * NT + w * 16 + g;
    uint32_t ah[4][4];
    {
        const char* Ah = (const char*)(g_ah + ((size_t)b * N_ + r0) * C_);
#pragma unroll
        for (int ks = 0; ks < 4; ks++) {
            int o0 = (ks * 16 + tig * 2) * 2;
            ah[ks][0] = *(const uint32_t*)(Ah + o0);
            ah[ks][1] = *(const uint32_t*)(Ah + 8 * C_ * 2 + o0);
            ah[ks][2] = *(const uint32_t*)(Ah + o0 + 16);
            ah[ks][3] = *(const uint32_t*)(Ah + 8 * C_ * 2 + o0 + 16);
        }
    }

    float wx0 = wkp[((size_t)b * N_ + r0) * 2 + 0];
    float wy0 = wkp[((size_t)b * N_ + r0) * 2 + 1];
    float wx1 = wkp[((size_t)b * N_ + r0 + 8) * 2 + 0];
    float wy1 = wkp[((size_t)b * N_ + r0 + 8) * 2 + 1];

    float t4a[4] = {3.0e38f, 3.0e38f, 3.0e38f, 3.0e38f};
    float t4b[4] = {3.0e38f, 3.0e38f, 3.0e38f, 3.0e38f};

    const uint4* Bh4 = (const uint4*)(g_bh + ((size_t)b * M_ + mbase0) * C_);

    auto fill = [&](int it, int buf) {
        uint32_t sbh = (uint32_t)__cvta_generic_to_shared(&sm_bh[buf][0]);
#pragma unroll
        for (int u = tid; u < CT * 8; u += 256) {
            int row = u >> 3, seg = u & 7;
            uint32_t off = (uint32_t)(row * 9 + seg) * 16;
            cp16(sbh + off, Bh4 + (size_t)(it * CT + row) * 8 + seg);
        }
    };

    fill(0, 0);
    CP_COMMIT();

    uint32_t soff = (uint32_t)((lane & 7) * (BSTRIDE_W * 4) + (lane >> 3) * 16);
    uint32_t sbh_base[2] = {
        (uint32_t)__cvta_generic_to_shared(&sm_bh[0][0]) + soff,
        (uint32_t)__cvta_generic_to_shared(&sm_bh[1][0]) + soff };

    for (int it = 0; it < ITERS; it++) {
        int cur = it & 1;
        if (it + 1 < ITERS) {
            fill(it + 1, 1 - cur);
            CP_COMMIT();
            CP_WAIT(1);
        } else {
            CP_WAIT(0);
        }
        __syncthreads();

        float cy  = (float)(chunk * (CHUNK / 64) + it) * 8.0f + 4.0f;
        float dy0 = wy0 - cy, dy02 = dy0 * dy0;
        float dy1 = wy1 - cy, dy12 = dy1 * dy1;

#pragma unroll
        for (int nt = 0; nt < 8; nt++) {
            float a0[4] = {0.f, 0.f, 0.f, 0.f};
            float a1[4] = {0.f, 0.f, 0.f, 0.f};
            uint32_t abase = (uint32_t)(nt * 8 * BSTRIDE_W * 4);

            uint32_t h0, h1, h2, h3, h4, h5, h6, h7;
            ldm_x4(h0, h1, h2, h3, sbh_base[cur] + abase);
            ldm_x4(h4, h5, h6, h7, sbh_base[cur] + abase + 64);
            mma_f16(a0, ah[0], h0, h1);
            mma_f16(a1, ah[1], h2, h3);
            mma_f16(a0, ah[2], h4, h5);
            mma_f16(a1, ah[3], h6, h7);

            int jl = nt * 8 + tig * 2;
            float cxa = (float)jl * 8.0f + 4.0f;
            float cxb = cxa + 8.0f;

            float d00 = fmaf(-2.0f, a0[0] + a1[0], 1.0f);
            float d01 = fmaf(-2.0f, a0[1] + a1[1], 1.0f);
            float d10 = fmaf(-2.0f, a0[2] + a1[2], 1.0f);
            float d11 = fmaf(-2.0f, a0[3] + a1[3], 1.0f);
            float dxa0 = wx0 - cxa, dxb0 = wx0 - cxb;
            float dxa1 = wx1 - cxa, dxb1 = wx1 - cxb;
            if (fmaf(dxa0, dxa0, dy02) <= 64.0f) d00 = 3.0e38f;
            if (fmaf(dxb0, dxb0, dy02) <= 64.0f) d01 = 3.0e38f;
            if (fmaf(dxa1, dxa1, dy12) <= 64.0f) d10 = 3.0e38f;
            if (fmaf(dxb1, dxb1, dy12) <= 64.0f) d11 = 3.0e38f;
            ins4(t4a, d00); ins4(t4a, d01);
            ins4(t4b, d10); ins4(t4b, d11);
        }
        __syncthreads();
    }

    // snapshot-based cross-lane top-4 merge
#pragma unroll
    for (int off = 1; off <= 2; off <<= 1) {
        float va[4], vb[4];
#pragma unroll
        for (int q = 0; q < 4; q++) {
            va[q] = __shfl_xor_sync(0xffffffffu, t4a[q], off);
            vb[q] = __shfl_xor_sync(0xffffffffu, t4b[q], off);
        }
#pragma unroll
        for (int q = 0; q < 4; q++) {
            ins4(t4a, va[q]);
            ins4(t4b, vb[q]);
        }
    }

    if (tig == 0) {
        size_t o0 = (((size_t)b * N_ + r0) * MSPLIT + chunk) * 4;
        size_t o1 = (((size_t)b * N_ + r0 + 8) * MSPLIT + chunk) * 4;
#pragma unroll
        for (int q = 0; q < 4; q++) {
            g_top4[o0 + q] = t4a[q];
            g_top4[o1 + q] = t4b[q];
        }
    }
}

// ---------------- 4) merge chunks + loss ----------------
__global__ void merge_kernel() {
    __shared__ float red[256];
    int idx = blockIdx.x * 256 + threadIdx.x;
    float best[4] = {3.0e38f, 3.0e38f, 3.0e38f, 3.0e38f};
    const float4* src = (const float4*)(g_top4 + (size_t)idx * (MSPLIT * 4));
#pragma unroll
    for (int q4 = 0; q4 < MSPLIT; q4++) {
        float4 v = src[q4];
        ins4(best, v.x); ins4(best, v.y); ins4(best, v.z); ins4(best, v.w);
    }
    float an = g_an[idx];
    float dp = g_dpos[idx];
    float contrib = 0.f;
#pragma unroll
    for (int q = 0; q < 4; q++) {
        float v = best[q];
        float d = (v > 1.0e37f) ? 1.0e6f : sqrtf(fmaxf(an + v, 0.f) + EPSF);
        contrib += fmaxf(dp - d + 1.0f, 0.f);
    }
    red[threadIdx.x] = contrib;
    __syncthreads();
#pragma unroll
    for (int o = 128; o; o >>= 1) {
        if (threadIdx.x < o) red[threadIdx.x] += red[threadIdx.x + o];
        __syncthreads();
    }
    if (threadIdx.x == 0) g_part2[blockIdx.x] = red[0];
}

__global__ void final_kernel(float* __restrict__ out) {
    if (threadIdx.x == 0) {
        float s = 0.f;
        for (int q = 0; q < 32; q++) s += g_part2[q];
        out[0] = s * (1.0f / (float)(B_ * N_ * 4));
    }
}

// ---------------- launch ----------------
extern "C" void kernel_launch(void* const* d_in, const int* in_sizes, int n_in,
                              void* d_out, int out_size) {
    const float* wkp   = (const float*)d_in[1];
    const float* kdesc = (const float*)d_in[2];
    const float* desc2 = (const float*)d_in[3];

    prep_kernel<<<PREP_GRID, 512>>>(wkp, kdesc, desc2);
    norm_kernel<<<B_ * M_, 32>>>();
    mma_kernel<<<dim3(N_ / NT, MSPLIT, B_), 256>>>(wkp);
    merge_kernel<<<32, 256>>>();
    final_kernel<<<1, 32>>>((float*)d_out);
}

// round 16
// speedup vs baseline: 1.0181x; 1.0181x over previous
#include <cuda_runtime.h>
#include <cuda_fp16.h>
#include <cstdint>
#include <math.h>

#define B_ 4
#define N_ 2048
#define C_ 64
#define H_ 512
#define W_ 512
#define GS 8
#define HG 64
#define WG 64
#define M_ 4096
#define EPSF 1e-8f

#define NT 128
#define CT 128                 // cells per tile (doubled)
#define MSPLIT 4
#define CHUNK (M_ / MSPLIT)    // 1024
#define ITERS (CHUNK / CT)     // 8

#define PB_POS   512
#define PB_POOL  (HG * C_ * B_)
#define PREP_GRID (PB_POS + PB_POOL)

// ---------------- scratch ----------------
__device__ float g_cells[B_ * M_ * C_];
__device__ float g_dpos[B_ * N_];
__device__ float g_an[B_ * N_];
__device__ __half g_ah[B_ * N_ * C_];
__device__ __half g_bh[B_ * M_ * C_];
__device__ float g_top4[B_ * N_ * MSPLIT * 4];
__device__ float g_part2[32];

__device__ __forceinline__ void mma_f16(float (&d)[4], const uint32_t (&a)[4],
                                        uint32_t b0, uint32_t b1) {
    asm volatile(
        "mma.sync.aligned.m16n8k16.row.col.f32.f16.f16.f32 "
        "{%0,%1,%2,%3}, {%4,%5,%6,%7}, {%8,%9}, {%0,%1,%2,%3};"
        : "+f"(d[0]), "+f"(d[1]), "+f"(d[2]), "+f"(d[3])
        : "r"(a[0]), "r"(a[1]), "r"(a[2]), "r"(a[3]), "r"(b0), "r"(b1));
}

__device__ __forceinline__ void ldm_x4(uint32_t& r0, uint32_t& r1, uint32_t& r2,
                                       uint32_t& r3, uint32_t addr) {
    asm volatile("ldmatrix.sync.aligned.m8n8.x4.shared.b16 {%0,%1,%2,%3}, [%4];"
                 : "=r"(r0), "=r"(r1), "=r"(r2), "=r"(r3) : "r"(addr));
}

__device__ __forceinline__ void cp16(uint32_t dst, const void* src) {
    asm volatile("cp.async.cg.shared.global [%0], [%1], 16;" :: "r"(dst), "l"(src));
}
#define CP_COMMIT() asm volatile("cp.async.commit_group;" ::: "memory")
#define CP_WAIT(n)  asm volatile("cp.async.wait_group %0;" :: "n"(n) : "memory")

// branchy top-4 insert: common path (d2 >= t[3]) is a uniform not-taken branch.
__device__ __forceinline__ void ins4(float (&t)[4], float d2) {
    if (d2 < t[3]) {
        if (d2 < t[2]) {
            t[3] = t[2];
            if (d2 < t[1]) {
                t[2] = t[1];
                if (d2 < t[0]) { t[1] = t[0]; t[0] = d2; }
                else t[1] = d2;
            } else t[2] = d2;
        } else t[3] = d2;
    }
}

// ---------------- 1) fused prep: (pos + conv_a) + pool ----------------
__global__ void __launch_bounds__(512) prep_kernel(const float* __restrict__ wkp,
                                                   const float* __restrict__ kdesc,
                                                   const float* __restrict__ desc2) {
    int p   = blockIdx.x;
    int tid = threadIdx.x;

    if (p < PB_POS) {
        int lane = tid & 31;
        int idx  = p * 16 + (tid >> 5);
        int b    = idx / N_;

        float x = wkp[(size_t)idx * 2 + 0];
        float y = wkp[(size_t)idx * 2 + 1];
        x = fminf(fmaxf(x, 0.0f), (float)(W_ - 1));
        y = fminf(fmaxf(y, 0.0f), (float)(H_ - 1));
        float x0f = floorf(x), y0f = floorf(y);
        int x0 = (int)x0f, y0 = (int)y0f;
        int x1 = min(x0 + 1, W_ - 1), y1 = min(y0 + 1, H_ - 1);
        float wx = x - x0f, wy = y - y0f;
        float w00 = (1.f - wy) * (1.f - wx);
        float w01 = (1.f - wy) * wx;
        float w10 = wy * (1.f - wx);
        float w11 = wy * wx;

        float v[2];
        float ss = 0.f;
#pragma unroll
        for (int q = 0; q < 2; q++) {
            int c = lane + q * 32;
            const float* pp = desc2 + ((size_t)(b * C_ + c) * H_) * W_;
            float f00 = pp[(size_t)y0 * W_ + x0];
            float f01 = pp[(size_t)y0 * W_ + x1];
            float f10 = pp[(size_t)y1 * W_ + x0];
            float f11 = pp[(size_t)y1 * W_ + x1];
            v[q] = w00 * f00 + w01 * f01 + w10 * f10 + w11 * f11;
            ss += v[q] * v[q];
        }
#pragma unroll
        for (int o = 16; o; o >>= 1) ss += __shfl_xor_sync(0xffffffffu, ss, o);
        float inv = 1.0f / (sqrtf(ss) + EPSF);

        float dsum = 0.f, asum = 0.f;
#pragma unroll
        for (int q = 0; q < 2; q++) {
            int c = lane + q * 32;
            float av = kdesc[(size_t)idx * C_ + c];
            g_ah[(size_t)idx * C_ + c] = __float2half(av);   // fused conv_a
            float d  = av - v[q] * inv;
            dsum += d * d;
            asum += av * av;
        }
#pragma unroll
        for (int o = 16; o; o >>= 1) {
            dsum += __shfl_xor_sync(0xffffffffu, dsum, o);
            asum += __shfl_xor_sync(0xffffffffu, asum, o);
        }
        if (lane == 0) {
            g_dpos[idx] = sqrtf(dsum + EPSF);
            g_an[idx]   = asum;
        }
    } else {
        int q2 = p - PB_POS;
        int hg = q2 & 63;
        int c  = (q2 >> 6) & 63;
        int b  = q2 >> 12;
        int col = tid;
        const float* pp = desc2 + (((size_t)(b * C_ + c) * H_) + hg * GS) * W_ + col;
        float s = 0.f;
#pragma unroll
        for (int r = 0; r < GS; r++) s += pp[(size_t)r * W_];
        s += __shfl_xor_sync(0xffffffffu, s, 1);
        s += __shfl_xor_sync(0xffffffffu, s, 2);
        s += __shfl_xor_sync(0xffffffffu, s, 4);
        if ((col & 7) == 0) {
            int wg = col >> 3;
            g_cells[((size_t)b * M_ + hg * WG + wg) * C_ + c] = s * (1.0f / 64.0f);
        }
    }
}

// ---------------- 2) normalize cells -> fp16 ----------------
__global__ void norm_kernel() {
    int idx  = blockIdx.x;
    int lane = threadIdx.x;
    const float* p = g_cells + (size_t)idx * C_;
    float v0 = p[lane], v1 = p[lane + 32];
    float ss = v0 * v0 + v1 * v1;
#pragma unroll
    for (int o = 16; o; o >>= 1) ss += __shfl_xor_sync(0xffffffffu, ss, o);
    float inv = 1.0f / (sqrtf(ss) + EPSF);
    g_bh[(size_t)idx * C_ + lane]      = __float2half(v0 * inv);
    g_bh[(size_t)idx * C_ + lane + 32] = __float2half(v1 * inv);
}

// ---------------- 3) HMMA fp16 GEMM + mask + top-4 (CT=128) ----------------
#define BSTRIDE_W 36   // words per padded cell row (72 fp16 = 144 B)

__global__ void __launch_bounds__(256, 2) mma_kernel(const float* __restrict__ wkp) {
    __shared__ uint4 sm_bh[2][CT * 9];   // 2 x 18432 B

    int tid   = threadIdx.x;
    int w     = tid >> 5;
    int lane  = tid & 31;
    int g     = lane >> 2;
    int tig   = lane & 3;
    int ntile = blockIdx.x;
    int chunk = blockIdx.y;
    int b     = blockIdx.z;

    int mbase0 = chunk * CHUNK;

    int r0 = ntile * NT + w * 16 + g;
    uint32_t ah[4][4];
    {
        const char* Ah = (const char*)(g_ah + ((size_t)b * N_ + r0) * C_);
#pragma unroll
        for (int ks = 0; ks < 4; ks++) {
            int o0 = (ks * 16 + tig * 2) * 2;
            ah[ks][0] = *(const uint32_t*)(Ah + o0);
            ah[ks][1] = *(const uint32_t*)(Ah + 8 * C_ * 2 + o0);
            ah[ks][2] = *(const uint32_t*)(Ah + o0 + 16);
            ah[ks][3] = *(const uint32_t*)(Ah + 8 * C_ * 2 + o0 + 16);
        }
    }

    float wx0 = wkp[((size_t)b * N_ + r0) * 2 + 0];
    float wy0 = wkp[((size_t)b * N_ + r0) * 2 + 1];
    float wx1 = wkp[((size_t)b * N_ + r0 + 8) * 2 + 0];
    float wy1 = wkp[((size_t)b * N_ + r0 + 8) * 2 + 1];

    float t4a[4] = {3.0e38f, 3.0e38f, 3.0e38f, 3.0e38f};
    float t4b[4] = {3.0e38f, 3.0e38f, 3.0e38f, 3.0e38f};

    const uint4* Bh4 = (const uint4*)(g_bh + ((size_t)b * M_ + mbase0) * C_);

    auto fill = [&](int it, int buf) {
        uint32_t sbh = (uint32_t)__cvta_generic_to_shared(&sm_bh[buf][0]);
#pragma unroll
        for (int u = tid; u < CT * 8; u += 256) {
            int row = u >> 3, seg = u & 7;
            uint32_t off = (uint32_t)(row * 9 + seg) * 16;
            cp16(sbh + off, Bh4 + (size_t)(it * CT + row) * 8 + seg);
        }
    };

    fill(0, 0);
    CP_COMMIT();

    uint32_t soff = (uint32_t)((lane & 7) * (BSTRIDE_W * 4) + (lane >> 3) * 16);
    uint32_t sbh_base[2] = {
        (uint32_t)__cvta_generic_to_shared(&sm_bh[0][0]) + soff,
        (uint32_t)__cvta_generic_to_shared(&sm_bh[1][0]) + soff };

    for (int it = 0; it < ITERS; it++) {
        int cur = it & 1;
        if (it + 1 < ITERS) {
            fill(it + 1, 1 - cur);
            CP_COMMIT();
            CP_WAIT(1);
        } else {
            CP_WAIT(0);
        }
        __syncthreads();

        // CT=128 spans 2 hg rows (64 cells each)
        int hgbase = (mbase0 + it * CT) >> 6;

#pragma unroll
        for (int nt = 0; nt < 16; nt++) {
            float a0[4] = {0.f, 0.f, 0.f, 0.f};
            float a1[4] = {0.f, 0.f, 0.f, 0.f};
            uint32_t abase = (uint32_t)(nt * 8 * BSTRIDE_W * 4);

            uint32_t h0, h1, h2, h3, h4, h5, h6, h7;
            ldm_x4(h0, h1, h2, h3, sbh_base[cur] + abase);
            ldm_x4(h4, h5, h6, h7, sbh_base[cur] + abase + 64);
            mma_f16(a0, ah[0], h0, h1);
            mma_f16(a1, ah[1], h2, h3);
            mma_f16(a0, ah[2], h4, h5);
            mma_f16(a1, ah[3], h6, h7);

            int jl  = nt * 8 + tig * 2;          // 0..127 within tile
            float cy  = (float)(hgbase + (jl >> 6)) * 8.0f + 4.0f;
            float dy0 = wy0 - cy, dy02 = dy0 * dy0;
            float dy1 = wy1 - cy, dy12 = dy1 * dy1;
            float cxa = (float)(jl & 63) * 8.0f + 4.0f;
            float cxb = cxa + 8.0f;

            float d00 = fmaf(-2.0f, a0[0] + a1[0], 1.0f);
            float d01 = fmaf(-2.0f, a0[1] + a1[1], 1.0f);
            float d10 = fmaf(-2.0f, a0[2] + a1[2], 1.0f);
            float d11 = fmaf(-2.0f, a0[3] + a1[3], 1.0f);
            float dxa0 = wx0 - cxa, dxb0 = wx0 - cxb;
            float dxa1 = wx1 - cxa, dxb1 = wx1 - cxb;
            if (fmaf(dxa0, dxa0, dy02) <= 64.0f) d00 = 3.0e38f;
            if (fmaf(dxb0, dxb0, dy02) <= 64.0f) d01 = 3.0e38f;
            if (fmaf(dxa1, dxa1, dy12) <= 64.0f) d10 = 3.0e38f;
            if (fmaf(dxb1, dxb1, dy12) <= 64.0f) d11 = 3.0e38f;
            ins4(t4a, d00); ins4(t4a, d01);
            ins4(t4b, d10); ins4(t4b, d11);
        }
        __syncthreads();
    }

    // snapshot-based cross-lane top-4 merge
#pragma unroll
    for (int off = 1; off <= 2; off <<= 1) {
        float va[4], vb[4];
#pragma unroll
        for (int q = 0; q < 4; q++) {
            va[q] = __shfl_xor_sync(0xffffffffu, t4a[q], off);
            vb[q] = __shfl_xor_sync(0xffffffffu, t4b[q], off);
        }
#pragma unroll
        for (int q = 0; q < 4; q++) {
            ins4(t4a, va[q]);
            ins4(t4b, vb[q]);
        }
    }

    if (tig == 0) {
        size_t o0 = (((size_t)b * N_ + r0) * MSPLIT + chunk) * 4;
        size_t o1 = (((size_t)b * N_ + r0 + 8) * MSPLIT + chunk) * 4;
#pragma unroll
        for (int q = 0; q < 4; q++) {
            g_top4[o0 + q] = t4a[q];
            g_top4[o1 + q] = t4b[q];
        }
    }
}

// ---------------- 4) merge chunks + loss ----------------
__global__ void merge_kernel() {
    __shared__ float red[256];
    int idx = blockIdx.x * 256 + threadIdx.x;
    float best[4] = {3.0e38f, 3.0e38f, 3.0e38f, 3.0e38f};
    const float4* src = (const float4*)(g_top4 + (size_t)idx * (MSPLIT * 4));
#pragma unroll
    for (int q4 = 0; q4 < MSPLIT; q4++) {
        float4 v = src[q4];
        ins4(best, v.x); ins4(best, v.y); ins4(best, v.z); ins4(best, v.w);
    }
    float an = g_an[idx];
    float dp = g_dpos[idx];
    float contrib = 0.f;
#pragma unroll
    for (int q = 0; q < 4; q++) {
        float v = best[q];
        float d = (v > 1.0e37f) ? 1.0e6f : sqrtf(fmaxf(an + v, 0.f) + EPSF);
        contrib += fmaxf(dp - d + 1.0f, 0.f);
    }
    red[threadIdx.x] = contrib;
    __syncthreads();
#pragma unroll
    for (int o = 128; o; o >>= 1) {
        if (threadIdx.x < o) red[threadIdx.x] += red[threadIdx.x + o];
        __syncthreads();
    }
    if (threadIdx.x == 0) g_part2[blockIdx.x] = red[0];
}

__global__ void final_kernel(float* __restrict__ out) {
    if (threadIdx.x == 0) {
        float s = 0.f;
        for (int q = 0; q < 32; q++) s += g_part2[q];
        out[0] = s * (1.0f / (float)(B_ * N_ * 4));
    }
}

// ---------------- launch ----------------
extern "C" void kernel_launch(void* const* d_in, const int* in_sizes, int n_in,
                              void* d_out, int out_size) {
    const float* wkp   = (const float*)d_in[1];
    const float* kdesc = (const float*)d_in[2];
    const float* desc2 = (const float*)d_in[3];

    prep_kernel<<<PREP_GRID, 512>>>(wkp, kdesc, desc2);
    norm_kernel<<<B_ * M_, 32>>>();
    mma_kernel<<<dim3(N_ / NT, MSPLIT, B_), 256>>>(wkp);
    merge_kernel<<<32, 256>>>();
    final_kernel<<<1, 32>>>((float*)d_out);
}

// round 17
// speedup vs baseline: 1.0872x; 1.0679x over previous
#include <cuda_runtime.h>
#include <cuda_fp16.h>
#include <cstdint>
#include <math.h>

#define B_ 4
#define N_ 2048
#define C_ 64
#define H_ 512
#define W_ 512
#define GS 8
#define HG 64
#define WG 64
#define M_ 4096
#define EPSF 1e-8f

#define NT 128
#define CT 64
#define MSPLIT 4
#define CHUNK (M_ / MSPLIT)    // 1024
#define ITERS (CHUNK / CT)     // 16

#define PB_POS   512
#define PB_POOL  (HG / 4 * C_ * B_)        // 4096 (4 hg rows per block)
#define PREP_GRID (PB_POS + PB_POOL)

// ---------------- scratch ----------------
__device__ float g_cells[B_ * M_ * C_];
__device__ float g_dpos[B_ * N_];
__device__ float g_an[B_ * N_];
__device__ __half g_ah[B_ * N_ * C_];
__device__ __half g_bh[B_ * M_ * C_];
__device__ float g_top4[B_ * N_ * MSPLIT * 4];
__device__ float g_part2[32];

__device__ __forceinline__ void mma_f16(float (&d)[4], const uint32_t (&a)[4],
                                        uint32_t b0, uint32_t b1) {
    asm volatile(
        "mma.sync.aligned.m16n8k16.row.col.f32.f16.f16.f32 "
        "{%0,%1,%2,%3}, {%4,%5,%6,%7}, {%8,%9}, {%0,%1,%2,%3};"
        : "+f"(d[0]), "+f"(d[1]), "+f"(d[2]), "+f"(d[3])
        : "r"(a[0]), "r"(a[1]), "r"(a[2]), "r"(a[3]), "r"(b0), "r"(b1));
}

__device__ __forceinline__ void ldm_x4(uint32_t& r0, uint32_t& r1, uint32_t& r2,
                                       uint32_t& r3, uint32_t addr) {
    asm volatile("ldmatrix.sync.aligned.m8n8.x4.shared.b16 {%0,%1,%2,%3}, [%4];"
                 : "=r"(r0), "=r"(r1), "=r"(r2), "=r"(r3) : "r"(addr));
}

__device__ __forceinline__ void cp16(uint32_t dst, const void* src) {
    asm volatile("cp.async.cg.shared.global [%0], [%1], 16;" :: "r"(dst), "l"(src));
}
#define CP_COMMIT() asm volatile("cp.async.commit_group;" ::: "memory")
#define CP_WAIT(n)  asm volatile("cp.async.wait_group %0;" :: "n"(n) : "memory")

// branchy top-4 insert: common path (d2 >= t[3]) is a uniform not-taken branch.
__device__ __forceinline__ void ins4(float (&t)[4], float d2) {
    if (d2 < t[3]) {
        if (d2 < t[2]) {
            t[3] = t[2];
            if (d2 < t[1]) {
                t[2] = t[1];
                if (d2 < t[0]) { t[1] = t[0]; t[0] = d2; }
                else t[1] = d2;
            } else t[2] = d2;
        } else t[3] = d2;
    }
}

// ---------------- 1) fused prep: (pos + conv_a) + pool(float4) ----------------
__global__ void __launch_bounds__(512) prep_kernel(const float* __restrict__ wkp,
                                                   const float* __restrict__ kdesc,
                                                   const float* __restrict__ desc2) {
    int p   = blockIdx.x;
    int tid = threadIdx.x;

    if (p < PB_POS) {
        int lane = tid & 31;
        int idx  = p * 16 + (tid >> 5);
        int b    = idx / N_;

        float x = wkp[(size_t)idx * 2 + 0];
        float y = wkp[(size_t)idx * 2 + 1];
        x = fminf(fmaxf(x, 0.0f), (float)(W_ - 1));
        y = fminf(fmaxf(y, 0.0f), (float)(H_ - 1));
        float x0f = floorf(x), y0f = floorf(y);
        int x0 = (int)x0f, y0 = (int)y0f;
        int x1 = min(x0 + 1, W_ - 1), y1 = min(y0 + 1, H_ - 1);
        float wx = x - x0f, wy = y - y0f;
        float w00 = (1.f - wy) * (1.f - wx);
        float w01 = (1.f - wy) * wx;
        float w10 = wy * (1.f - wx);
        float w11 = wy * wx;

        float v[2];
        float ss = 0.f;
#pragma unroll
        for (int q = 0; q < 2; q++) {
            int c = lane + q * 32;
            const float* pp = desc2 + ((size_t)(b * C_ + c) * H_) * W_;
            float f00 = pp[(size_t)y0 * W_ + x0];
            float f01 = pp[(size_t)y0 * W_ + x1];
            float f10 = pp[(size_t)y1 * W_ + x0];
            float f11 = pp[(size_t)y1 * W_ + x1];
            v[q] = w00 * f00 + w01 * f01 + w10 * f10 + w11 * f11;
            ss += v[q] * v[q];
        }
#pragma unroll
        for (int o = 16; o; o >>= 1) ss += __shfl_xor_sync(0xffffffffu, ss, o);
        float inv = 1.0f / (sqrtf(ss) + EPSF);

        float dsum = 0.f, asum = 0.f;
#pragma unroll
        for (int q = 0; q < 2; q++) {
            int c = lane + q * 32;
            float av = kdesc[(size_t)idx * C_ + c];
            g_ah[(size_t)idx * C_ + c] = __float2half(av);   // fused conv_a
            float d  = av - v[q] * inv;
            dsum += d * d;
            asum += av * av;
        }
#pragma unroll
        for (int o = 16; o; o >>= 1) {
            dsum += __shfl_xor_sync(0xffffffffu, dsum, o);
            asum += __shfl_xor_sync(0xffffffffu, asum, o);
        }
        if (lane == 0) {
            g_dpos[idx] = sqrtf(dsum + EPSF);
            g_an[idx]   = asum;
        }
    } else {
        // pool: block handles (b, c, 4 hg rows); thread loads one float4 per row.
        int q2    = p - PB_POS;            // 0..4095
        int hg4   = q2 & 15;
        int c     = (q2 >> 4) & 63;
        int b     = q2 >> 10;
        int strip = tid >> 7;              // 0..3
        int t     = tid & 127;             // 128 threads x 4 cols = 512 cols
        int hg    = hg4 * 4 + strip;

        const float4* pp = (const float4*)(desc2 +
            (((size_t)(b * C_ + c) * H_) + hg * GS) * W_) + t;
        float s = 0.f;
#pragma unroll
        for (int r = 0; r < GS; r++) {
            float4 v = pp[(size_t)r * (W_ / 4)];
            s += (v.x + v.y) + (v.z + v.w);
        }
        s += __shfl_xor_sync(0xffffffffu, s, 1);   // pair covers 8 cols = 1 cell
        if ((t & 1) == 0) {
            int wg = t >> 1;
            g_cells[((size_t)b * M_ + hg * WG + wg) * C_ + c] = s * (1.0f / 64.0f);
        }
    }
}

// ---------------- 2) normalize cells -> fp16 (8 cells per 256-thread block) ----------------
__global__ void __launch_bounds__(256) norm_kernel() {
    int idx  = blockIdx.x * 8 + (threadIdx.x >> 5);   // cell index
    int lane = threadIdx.x & 31;
    const float* p = g_cells + (size_t)idx * C_;
    float v0 = p[lane], v1 = p[lane + 32];
    float ss = v0 * v0 + v1 * v1;
#pragma unroll
    for (int o = 16; o; o >>= 1) ss += __shfl_xor_sync(0xffffffffu, ss, o);
    float inv = 1.0f / (sqrtf(ss) + EPSF);
    g_bh[(size_t)idx * C_ + lane]      = __float2half(v0 * inv);
    g_bh[(size_t)idx * C_ + lane + 32] = __float2half(v1 * inv);
}

// ---------------- 3) HMMA fp16 GEMM + mask + top-4 (R14 shape) ----------------
#define BSTRIDE_W 36   // words per padded cell row (72 fp16 = 144 B)

__global__ void __launch_bounds__(256, 2) mma_kernel(const float* __restrict__ wkp) {
    __shared__ uint4 sm_bh[2][CT * 9];

    int tid   = threadIdx.x;
    int w     = tid >> 5;
    int lane  = tid & 31;
    int g     = lane >> 2;
    int tig   = lane & 3;
    int ntile = blockIdx.x;
    int chunk = blockIdx.y;
    int b     = blockIdx.z;

    int mbase0 = chunk * CHUNK;

    int r0 = ntile * NT + w * 16 + g;
    uint32_t ah[4][4];
    {
        const char* Ah = (const char*)(g_ah + ((size_t)b * N_ + r0) * C_);
#pragma unroll
        for (int ks = 0; ks < 4; ks++) {
            int o0 = (ks * 16 + tig * 2) * 2;
            ah[ks][0] = *(const uint32_t*)(Ah + o0);
            ah[ks][1] = *(const uint32_t*)(Ah + 8 * C_ * 2 + o0);
            ah[ks][2] = *(const uint32_t*)(Ah + o0 + 16);
            ah[ks][3] = *(const uint32_t*)(Ah + 8 * C_ * 2 + o0 + 16);
        }
    }

    float wx0 = wkp[((size_t)b * N_ + r0) * 2 + 0];
    float wy0 = wkp[((size_t)b * N_ + r0) * 2 + 1];
    float wx1 = wkp[((size_t)b * N_ + r0 + 8) * 2 + 0];
    float wy1 = wkp[((size_t)b * N_ + r0 + 8) * 2 + 1];

    float t4a[4] = {3.0e38f, 3.0e38f, 3.0e38f, 3.0e38f};
    float t4b[4] = {3.0e38f, 3.0e38f, 3.0e38f, 3.0e38f};

    const uint4* Bh4 = (const uint4*)(g_bh + ((size_t)b * M_ + mbase0) * C_);

    auto fill = [&](int it, int buf) {
        uint32_t sbh = (uint32_t)__cvta_generic_to_shared(&sm_bh[buf][0]);
#pragma unroll
        for (int u = tid; u < CT * 8; u += 256) {
            int row = u >> 3, seg = u & 7;
            uint32_t off = (uint32_t)(row * 9 + seg) * 16;
            cp16(sbh + off, Bh4 + (size_t)(it * CT + row) * 8 + seg);
        }
    };

    fill(0, 0);
    CP_COMMIT();

    uint32_t soff = (uint32_t)((lane & 7) * (BSTRIDE_W * 4) + (lane >> 3) * 16);
    uint32_t sbh_base[2] = {
        (uint32_t)__cvta_generic_to_shared(&sm_bh[0][0]) + soff,
        (uint32_t)__cvta_generic_to_shared(&sm_bh[1][0]) + soff };

    for (int it = 0; it < ITERS; it++) {
        int cur = it & 1;
        if (it + 1 < ITERS) {
            fill(it + 1, 1 - cur);
            CP_COMMIT();
            CP_WAIT(1);
        } else {
            CP_WAIT(0);
        }
        __syncthreads();

        float cy  = (float)(chunk * (CHUNK / 64) + it) * 8.0f + 4.0f;
        float dy0 = wy0 - cy, dy02 = dy0 * dy0;
        float dy1 = wy1 - cy, dy12 = dy1 * dy1;

#pragma unroll
        for (int nt = 0; nt < 8; nt++) {
            float a0[4] = {0.f, 0.f, 0.f, 0.f};
            float a1[4] = {0.f, 0.f, 0.f, 0.f};
            uint32_t abase = (uint32_t)(nt * 8 * BSTRIDE_W * 4);

            uint32_t h0, h1, h2, h3, h4, h5, h6, h7;
            ldm_x4(h0, h1, h2, h3, sbh_base[cur] + abase);
            ldm_x4(h4, h5, h6, h7, sbh_base[cur] + abase + 64);
            mma_f16(a0, ah[0], h0, h1);
            mma_f16(a1, ah[1], h2, h3);
            mma_f16(a0, ah[2], h4, h5);
            mma_f16(a1, ah[3], h6, h7);

            int jl = nt * 8 + tig * 2;
            float cxa = (float)jl * 8.0f + 4.0f;
            float cxb = cxa + 8.0f;

            float d00 = fmaf(-2.0f, a0[0] + a1[0], 1.0f);
            float d01 = fmaf(-2.0f, a0[1] + a1[1], 1.0f);
            float d10 = fmaf(-2.0f, a0[2] + a1[2], 1.0f);
            float d11 = fmaf(-2.0f, a0[3] + a1[3], 1.0f);
            float dxa0 = wx0 - cxa, dxb0 = wx0 - cxb;
            float dxa1 = wx1 - cxa, dxb1 = wx1 - cxb;
            if (fmaf(dxa0, dxa0, dy02) <= 64.0f) d00 = 3.0e38f;
            if (fmaf(dxb0, dxb0, dy02) <= 64.0f) d01 = 3.0e38f;
            if (fmaf(dxa1, dxa1, dy12) <= 64.0f) d10 = 3.0e38f;
            if (fmaf(dxb1, dxb1, dy12) <= 64.0f) d11 = 3.0e38f;
            ins4(t4a, d00); ins4(t4a, d01);
            ins4(t4b, d10); ins4(t4b, d11);
        }
        __syncthreads();
    }

    // snapshot-based cross-lane top-4 merge
#pragma unroll
    for (int off = 1; off <= 2; off <<= 1) {
        float va[4], vb[4];
#pragma unroll
        for (int q = 0; q < 4; q++) {
            va[q] = __shfl_xor_sync(0xffffffffu, t4a[q], off);
            vb[q] = __shfl_xor_sync(0xffffffffu, t4b[q], off);
        }
#pragma unroll
        for (int q = 0; q < 4; q++) {
            ins4(t4a, va[q]);
            ins4(t4b, vb[q]);
        }
    }

    if (tig == 0) {
        size_t o0 = (((size_t)b * N_ + r0) * MSPLIT + chunk) * 4;
        size_t o1 = (((size_t)b * N_ + r0 + 8) * MSPLIT + chunk) * 4;
#pragma unroll
        for (int q = 0; q < 4; q++) {
            g_top4[o0 + q] = t4a[q];
            g_top4[o1 + q] = t4b[q];
        }
    }
}

// ---------------- 4) merge chunks + loss ----------------
__global__ void merge_kernel() {
    __shared__ float red[256];
    int idx = blockIdx.x * 256 + threadIdx.x;
    float best[4] = {3.0e38f, 3.0e38f, 3.0e38f, 3.0e38f};
    const float4* src = (const float4*)(g_top4 + (size_t)idx * (MSPLIT * 4));
#pragma unroll
    for (int q4 = 0; q4 < MSPLIT; q4++) {
        float4 v = src[q4];
        ins4(best, v.x); ins4(best, v.y); ins4(best, v.z); ins4(best, v.w);
    }
    float an = g_an[idx];
    float dp = g_dpos[idx];
    float contrib = 0.f;
#pragma unroll
    for (int q = 0; q < 4; q++) {
        float v = best[q];
        float d = (v > 1.0e37f) ? 1.0e6f : sqrtf(fmaxf(an + v, 0.f) + EPSF);
        contrib += fmaxf(dp - d + 1.0f, 0.f);
    }
    red[threadIdx.x] = contrib;
    __syncthreads();
#pragma unroll
    for (int o = 128; o; o >>= 1) {
        if (threadIdx.x < o) red[threadIdx.x] += red[threadIdx.x + o];
        __syncthreads();
    }
    if (threadIdx.x == 0) g_part2[blockIdx.x] = red[0];
}

__global__ void final_kernel(float* __restrict__ out) {
    if (threadIdx.x == 0) {
        float s = 0.f;
        for (int q = 0; q < 32; q++) s += g_part2[q];
        out[0] = s * (1.0f / (float)(B_ * N_ * 4));
    }
}

// ---------------- launch ----------------
extern "C" void kernel_launch(void* const* d_in, const int* in_sizes, int n_in,
                              void* d_out, int out_size) {
    const float* wkp   = (const float*)d_in[1];
    const float* kdesc = (const float*)d_in[2];
    const float* desc2 = (const float*)d_in[3];

    prep_kernel<<<PREP_GRID, 512>>>(wkp, kdesc, desc2);
    norm_kernel<<<B_ * M_ / 8, 256>>>();
    mma_kernel<<<dim3(N_ / NT, MSPLIT, B_), 256>>>(wkp);
    merge_kernel<<<32, 256>>>();
    final_kernel<<<1, 32>>>((float*)d_out);
}